// round 17
// baseline (speedup 1.0000x reference)
#include <cuda_runtime.h>

#define E    4096
#define NVAR 1024
#define NCHK 512
#define EPS32   1.1920929e-07f
#define LN2F    0.6931471805599453f

// Upper-triangle peers of each edge (columns > row), UNORDERED within a row
// (slots reserved via atomicAdd). Rows with g_cnt==7 are check
// representatives; only their lists are read by decode, which sorts the 7
// peers in registers. decode resets g_cnt after reading so every graph
// replay starts from zero (stream-ordered: reset precedes the next build).
__device__ int g_up[E * 7];
__device__ __align__(16) int g_cnt[E];

// ---------------- kernel A: eighth-row upper-triangle scan -------------------
// 32768 warps, warp = (row, eighth). Serial depth FOUR unconditional
// immediate-offset LDG.128 per warp (vs 16 before) and eighths wholly on/below
// the diagonal are skipped outright -> ~36MB touched with maximal MLP.
// Common path per chunk: load + uint OR + one ballot. The rare warp-uniform
// branch masks cols>row, reserves slots with ONE atomicAdd per warp-chunk,
// and scatters the found columns (unordered across chunks/eighths).
__global__ void build_peers_kernel(const uint4* __restrict__ w) {
    const int gw   = (blockIdx.x * blockDim.x + threadIdx.x) >> 5;  // 0..32767
    const int lane = threadIdx.x & 31;
    const int row  = gw >> 3;
    const int s    = gw & 7;
    if (row >= 512 * (s + 1) - 1) return;    // eighth has no col > row
    const uint4* base = w + (size_t)row * (E / 4) + s * 128 + lane;
    int* dst = g_up + row * 7;
    const int colb = s * 512 + lane * 4;
#pragma unroll
    for (int i = 0; i < 4; i++) {
        uint4 v = base[i * 32];                      // unconditional, imm offset
        unsigned nz = v.x | v.y | v.z | v.w;
        if (__ballot_sync(0xffffffffu, nz != 0u)) {  // warp-uniform, rare
            int col = colb + i * 128;
            int c0 = (v.x != 0u) & (col     > row);
            int c1 = (v.y != 0u) & (col + 1 > row);
            int c2 = (v.z != 0u) & (col + 2 > row);
            int c3 = (v.w != 0u) & (col + 3 > row);
            int cnt = c0 + c1 + c2 + c3;
            unsigned b0 = __ballot_sync(0xffffffffu, cnt & 1);
            unsigned b1 = __ballot_sync(0xffffffffu, cnt & 2);
            unsigned b2 = __ballot_sync(0xffffffffu, cnt & 4);
            int tot = __popc(b0) + 2 * __popc(b1) + 4 * __popc(b2);
            if (tot) {                               // warp-uniform
                int wbase = 0;
                if (lane == 0) wbase = atomicAdd(&g_cnt[row], tot);
                wbase = __shfl_sync(0xffffffffu, wbase, 0);
                unsigned lo = (1u << lane) - 1u;
                int idx = wbase + __popc(b0 & lo) + 2 * __popc(b1 & lo)
                                + 4 * __popc(b2 & lo);
                if (c0) dst[idx++] = col;
                if (c1) dst[idx++] = col + 1;
                if (c2) dst[idx++] = col + 2;
                if (c3) dst[idx]   = col + 3;
            }
        }
    }
}

// ---------------- math helpers -----------------------------------------------
__device__ __forceinline__ float tanh_acc(float a) {
    // tanh(a) = 1 - 2/(exp(2a)+1); inf-safe (saturates to +-1 exactly)
    return 1.0f - __fdividef(2.0f, __expf(2.0f * a) + 1.0f);
}

__device__ __forceinline__ float atanh2(float v) {
    // reference clamps: v>=1 -> 1-eps, v<=-1 -> -1+eps (exact copy)
    v = (v >= 1.0f) ? (1.0f - EPS32) : v;
    v = (v <= -1.0f) ? (-1.0f + EPS32) : v;
    // 2*atanh(v) = ln2*(lg2(1+v) - lg2(1-v)); two independent MUFU lg2
    return LN2F * (__log2f(1.0f + v) - __log2f(1.0f - v));
}

__device__ __forceinline__ float zsub(float o) {
    return (o == 0.0f) ? 1.0f : o;   // reference maps exact zeros -> identity
}

// compare-swap on named registers (ascending)
#define CAS(a, b) { int _lo = min(a, b), _hi = max(a, b); a = _lo; b = _hi; }

// ---------------- kernel B: full decode, one persistent block ----------------
__global__ __launch_bounds__(1024, 1)
void decode_kernel(const float* __restrict__ x, float* __restrict__ out) {
    __shared__ float sh_odd[E];      // odd messages, natural edge order
    __shared__ float sh_even[E];     // even messages, natural edge order
    __shared__ int   chk_list[NCHK]; // representative (min) edge per check
    __shared__ int   chk_ctr;

    const int t = threadIdx.x;
    const float llr = x[t];

    if (t == 0) chk_ctr = 0;
    ((float4*)sh_even)[t] = make_float4(0.f, 0.f, 0.f, 0.f);
    __syncthreads();

    // claim checks: edge e is representative iff all 7 peers are above it;
    // then reset the counters so the next graph replay starts from zero.
    int4 cc = ((const int4*)g_cnt)[t];
    ((int4*)g_cnt)[t] = make_int4(0, 0, 0, 0);
    if (cc.x == 7) chk_list[atomicAdd(&chk_ctr, 1)] = 4 * t;
    if (cc.y == 7) chk_list[atomicAdd(&chk_ctr, 1)] = 4 * t + 1;
    if (cc.z == 7) chk_list[atomicAdd(&chk_ctr, 1)] = 4 * t + 2;
    if (cc.w == 7) chk_list[atomicAdd(&chk_ctr, 1)] = 4 * t + 3;
    __syncthreads();

    // check owners load their 7 (unordered) peers and sort them in registers
    // (fully-unrolled bubble network, static register names -> no local mem).
    // Sorting canonicalizes product order: bitwise-identical across replays.
    int id0 = 0, id1 = 0, id2 = 0, id3 = 0, id4 = 0, id5 = 0, id6 = 0, id7 = 0;
    if (t < NCHK) {
        int rep = chk_list[t];
        const int* pp = g_up + rep * 7;
        id0 = rep;                       // rep is the check's minimum edge
        id1 = pp[0]; id2 = pp[1]; id3 = pp[2]; id4 = pp[3];
        id5 = pp[4]; id6 = pp[5]; id7 = pp[6];
        CAS(id1, id2); CAS(id3, id4); CAS(id5, id6);               // bubble p1
        CAS(id2, id3); CAS(id4, id5); CAS(id6, id7);
        CAS(id1, id2); CAS(id3, id4); CAS(id5, id6);               // pass 2
        CAS(id2, id3); CAS(id4, id5);
        CAS(id1, id2); CAS(id3, id4); CAS(id5, id6);               // pass 3
        CAS(id2, id3); CAS(id4, id5);
        CAS(id3, id4);                                             // settle
        CAS(id2, id3); CAS(id4, id5);
        CAS(id3, id4);
    }

    // ---- 5 BP iterations ------------------------------------------------------
#pragma unroll 1
    for (int it = 0; it < 5; it++) {
        // odd stage: vectorized, natural order (thread t = variable t)
        float4 ev = ((float4*)sh_even)[t];
        float vs = ev.x + ev.y + ev.z + ev.w;
        float4 od;
        od.x = tanh_acc(0.5f * (llr + vs - ev.x));
        od.y = tanh_acc(0.5f * (llr + vs - ev.y));
        od.z = tanh_acc(0.5f * (llr + vs - ev.z));
        od.w = tanh_acc(0.5f * (llr + vs - ev.w));
        ((float4*)sh_odd)[t] = od;
        __syncthreads();

        // even stage: 512 check owners gather 8, extrinsic products, scatter 8
        if (t < NCHK) {
            float a0 = zsub(sh_odd[id0]), a1 = zsub(sh_odd[id1]);
            float a2 = zsub(sh_odd[id2]), a3 = zsub(sh_odd[id3]);
            float a4 = zsub(sh_odd[id4]), a5 = zsub(sh_odd[id5]);
            float a6 = zsub(sh_odd[id6]), a7 = zsub(sh_odd[id7]);
            float p01 = a0 * a1, p23 = a2 * a3, p45 = a4 * a5, p67 = a6 * a7;
            float q03 = p01 * p23, q47 = p45 * p67;
            sh_even[id0] = atanh2(a1 * p23 * q47);
            sh_even[id1] = atanh2(a0 * p23 * q47);
            sh_even[id2] = atanh2(p01 * a3 * q47);
            sh_even[id3] = atanh2(p01 * a2 * q47);
            sh_even[id4] = atanh2(q03 * a5 * p67);
            sh_even[id5] = atanh2(q03 * a4 * p67);
            sh_even[id6] = atanh2(q03 * p45 * a7);
            sh_even[id7] = atanh2(q03 * p45 * a6);
        }
        __syncthreads();
    }

    // ---- epilogue: out[n] = sigmoid(x[n] + sum of even over var n) ------------
    float4 ev = ((float4*)sh_even)[t];
    float z = llr + ev.x + ev.y + ev.z + ev.w;
    out[t] = __fdividef(1.0f, 1.0f + __expf(-z));
}

// ---------------- launch ------------------------------------------------------
extern "C" void kernel_launch(void* const* d_in, const int* in_sizes, int n_in,
                              void* d_out, int out_size) {
    (void)in_sizes; (void)n_in; (void)out_size;
    const float* x = (const float*)d_in[0];
    const uint4* w = (const uint4*)d_in[2];   // w_odd_to_even [E,E]
    float* out = (float*)d_out;

    build_peers_kernel<<<4096, 256>>>(w);   // 32768 eighth-row warps, depth 4
    decode_kernel<<<1, 1024>>>(x, out);
}